// round 11
// baseline (speedup 1.0000x reference)
#include <cuda_runtime.h>
#include <cstdint>

// Problem constants  (V,E,H,T = 32000, 512, 1024, 4096)
#define EMB    512
#define T_SEQ  4096
#define HID    1024
#define G4H    4096          // 4*HID
#define VOC    32000
#define NBLK   128           // recurrence blocks (co-resident, 1/SM)
#define NSTEPS (2*T_SEQ - 1) // 4096 encoder + 4095 decoder = 8191

// ---------------- device scratch (static: no runtime allocation) ----------------
__device__ float g_ih_enc[(size_t)T_SEQ * G4H];       // 64 MB
__device__ float g_ih_dec[(size_t)(T_SEQ-1) * G4H];   // 64 MB
__device__ float g_hs[(size_t)(T_SEQ-1) * HID];       // 16.8 MB
__device__ unsigned long long g_slots[2 * HID];       // (tag,value) pairs, double-buffered

// ---------------- single-instruction 64-bit generic accesses ----------------
__device__ __forceinline__ void slot_store(unsigned long long* p, unsigned long long v) {
    asm volatile("st.relaxed.gpu.b64 [%0], %1;" :: "l"(p), "l"(v) : "memory");
}
__device__ __forceinline__ unsigned long long slot_load(const unsigned long long* p) {
    unsigned long long v;
    asm volatile("ld.relaxed.gpu.b64 %0, [%1];" : "=l"(v) : "l"(p) : "memory");
    return v;
}

// ---------------- packed f32x2 helpers (bit-equivalence vs FFMA confirmed R1-vs-R3) ----
__device__ __forceinline__ unsigned long long pack2f(float x) {
    unsigned long long r;
    asm("mov.b64 %0, {%1, %1};" : "=l"(r) : "f"(x));
    return r;
}
__device__ __forceinline__ void ffma2(unsigned long long& d, unsigned long long a, unsigned long long b) {
    asm("fma.rn.f32x2 %0, %1, %2, %0;" : "+l"(d) : "l"(a), "l"(b));
}
__device__ __forceinline__ float lo2(unsigned long long v) { return __uint_as_float((unsigned)v); }
__device__ __forceinline__ float hi2(unsigned long long v) { return __uint_as_float((unsigned)(v >> 32)); }

// fast sigmoid/tanh via MUFU (__expf); error ~1e-6, budget 1e-3
__device__ __forceinline__ float sigm_f(float x) { return __frcp_rn(1.0f + __expf(-x)); }
__device__ __forceinline__ float tanh_f(float x) { return 2.0f * __frcp_rn(1.0f + __expf(-2.0f * x)) - 1.0f; }

// ---------------- init kernel (reset sync state each launch) ----------------
__global__ void init_kernel() {
    int i = blockIdx.x * blockDim.x + threadIdx.x;
    if (i < 2 * HID) g_slots[i] = ~0ull;   // tag never matches a real step
}

// ---------------- NT GEMM: C[M,N] = Arow(m) . B[n,:] + bias1[n] (+bias2[n]) ----
// 128x128 tile, 256 threads, 8x8 micro-tile in packed f32x2 accumulators.
// Register-prefetch software pipeline: tile k+1 LDG in flight while computing tile k.
// A rows: if gidx != null, row m = tab[gidx[m]] (length K), else A + m*K.
// K: runtime, multiple of 16. N multiple of 128. M guarded.
#define BM 128
#define BN 128
#define BKT 16
#define PAD 132

__global__ __launch_bounds__(256, 2)
void gemm_nt(const float* __restrict__ A, const float* __restrict__ tab,
             const int* __restrict__ gidx, const float* __restrict__ B,
             const float* __restrict__ bias1, const float* __restrict__ bias2,
             float* __restrict__ C, int M, int N, int K)
{
    __shared__ float As[BKT][PAD];
    __shared__ float Bs[BKT][PAD];
    __shared__ int sidx[BM];

    const int tid = threadIdx.x;
    const int bm = blockIdx.y, bn = blockIdx.x;
    const int row0 = bm * BM;

    if (gidx && tid < BM) {
        int r = row0 + tid; if (r >= M) r = M - 1;
        sidx[tid] = gidx[r];
    }
    __syncthreads();

    const int tx = tid & 15, ty = tid >> 4;

    // per-thread load pointers for the two 256-thread sweeps (t=0,1)
    const float* apt[2]; const float* bpt[2];
    int arow_[2], kq_[2];
#pragma unroll
    for (int t = 0; t < 2; t++) {
        int idx  = tid + t * 256;
        int arow = idx >> 2, kq = idx & 3;
        arow_[t] = arow; kq_[t] = kq;
        int grA = row0 + arow; if (grA >= M) grA = M - 1;
        apt[t] = (gidx ? (tab + (size_t)sidx[arow] * K)
                       : (A + (size_t)grA * K)) + kq * 4;
        bpt[t] = B + (size_t)(bn * BN + arow) * K + kq * 4;
    }

    unsigned long long acc[8][4];
#pragma unroll
    for (int i = 0; i < 8; i++)
#pragma unroll
        for (int j = 0; j < 4; j++) acc[i][j] = 0ull;

    const int NT = K / BKT;
    float4 ra[2], rb[2];
#pragma unroll
    for (int t = 0; t < 2; t++) {           // prologue: tile 0
        ra[t] = *(const float4*)(apt[t]);
        rb[t] = *(const float4*)(bpt[t]);
    }

    for (int kt = 0; kt < NT; kt++) {
#pragma unroll
        for (int t = 0; t < 2; t++) {       // commit tile kt to smem
            int arow = arow_[t], kq = kq_[t];
            As[kq * 4 + 0][arow] = ra[t].x; As[kq * 4 + 1][arow] = ra[t].y;
            As[kq * 4 + 2][arow] = ra[t].z; As[kq * 4 + 3][arow] = ra[t].w;
            Bs[kq * 4 + 0][arow] = rb[t].x; Bs[kq * 4 + 1][arow] = rb[t].y;
            Bs[kq * 4 + 2][arow] = rb[t].z; Bs[kq * 4 + 3][arow] = rb[t].w;
        }
        __syncthreads();

        if (kt + 1 < NT) {                  // prefetch tile kt+1 (latency under compute)
            int off = (kt + 1) * BKT;
#pragma unroll
            for (int t = 0; t < 2; t++) {
                ra[t] = *(const float4*)(apt[t] + off);
                rb[t] = *(const float4*)(bpt[t] + off);
            }
        }

#pragma unroll
        for (int kk = 0; kk < BKT; kk++) {
            float4 a0 = *(const float4*)&As[kk][ty * 4];
            float4 a1 = *(const float4*)&As[kk][64 + ty * 4];
            const unsigned long long* bu = (const unsigned long long*)&Bs[kk][0];
            unsigned long long b0 = bu[tx * 2],      b1 = bu[tx * 2 + 1];
            unsigned long long b2 = bu[32 + tx * 2], b3 = bu[32 + tx * 2 + 1];
            float am[8] = {a0.x, a0.y, a0.z, a0.w, a1.x, a1.y, a1.z, a1.w};
#pragma unroll
            for (int i = 0; i < 8; i++) {
                unsigned long long aa = pack2f(am[i]);
                ffma2(acc[i][0], aa, b0);
                ffma2(acc[i][1], aa, b1);
                ffma2(acc[i][2], aa, b2);
                ffma2(acc[i][3], aa, b3);
            }
        }
        __syncthreads();
    }

    // epilogue
    const int ncol0 = bn * BN + tx * 4;
    const int ncol1 = bn * BN + 64 + tx * 4;
    float bv[8];
#pragma unroll
    for (int j = 0; j < 4; j++) { bv[j] = bias1[ncol0 + j]; bv[4 + j] = bias1[ncol1 + j]; }
    if (bias2) {
#pragma unroll
        for (int j = 0; j < 4; j++) { bv[j] += bias2[ncol0 + j]; bv[4 + j] += bias2[ncol1 + j]; }
    }
#pragma unroll
    for (int i = 0; i < 8; i++) {
        int mloc = (i < 4) ? (ty * 4 + i) : (64 + ty * 4 + (i - 4));
        int m = row0 + mloc;
        if (m < M) {
            float* cp = C + (size_t)m * N;
            float4 o0, o1;
            o0.x = lo2(acc[i][0]) + bv[0]; o0.y = hi2(acc[i][0]) + bv[1];
            o0.z = lo2(acc[i][1]) + bv[2]; o0.w = hi2(acc[i][1]) + bv[3];
            o1.x = lo2(acc[i][2]) + bv[4]; o1.y = hi2(acc[i][2]) + bv[5];
            o1.z = lo2(acc[i][3]) + bv[6]; o1.w = hi2(acc[i][3]) + bv[7];
            *(float4*)(cp + ncol0) = o0;
            *(float4*)(cp + ncol1) = o1;
        }
    }
}

// ---------------- persistent recurrence kernel ----------------
// Block b owns h elements [8b, 8b+8) -> 32 gate rows. Warp w = gate row:
// gi = w>>3 (gate), jrow = w&7 (element), global row grow = gi*1024 + 8b + jrow.
// Lane l owns columns {l, l+32, ..., l+992}; warp shuffle reduce -> part[w].
// Group sync: warps {jj, 8+jj, 16+jj, 24+jj} meet at named barrier (1+jj, 128);
// finalize for element jj runs in warp jj lane 0 (cell state in register),
// publishing its slot as soon as ITS group is done (no full-block coupling).
// Cross-block sync: tag-polled double-buffered (tag|h) u64 slots in L2.
// Deadlock-free: tag s overwritten only at step s+2, which requires all blocks
// to have consumed tag s.

__global__ __launch_bounds__(1024, 1)
void recurrence(const float* __restrict__ encWhh, const float* __restrict__ decWhh)
{
    __shared__ float hs_sh[HID];
    __shared__ float part[32];

    const int tid = threadIdx.x;
    const int b = blockIdx.x;
    const int w = tid >> 5, l = tid & 31;
    const int gi = w >> 3, jrow = w & 7;
    const int grow = gi * HID + 8 * b + jrow;
    const bool fin = (w < 8) && (l == 0);   // finalizer for element jj = w

    float Wreg[32];
    {
        const float* rp = encWhh + (size_t)grow * HID;
#pragma unroll
        for (int c = 0; c < 32; c++) Wreg[c] = __ldg(rp + l + 32 * c);
    }
    float c_reg = 0.0f;                     // cell state (finalizer threads only)
    __syncthreads();

    for (int sc = 0; sc < NSTEPS; sc++) {
        if (sc == T_SEQ) {   // switch to decoder weights (registers only)
            const float* rp = decWhh + (size_t)grow * HID;
#pragma unroll
            for (int c = 0; c < 32; c++) Wreg[c] = __ldg(rp + l + 32 * c);
        }
        const bool enc = sc < T_SEQ;
        const int tstep = enc ? sc : sc - T_SEQ;
        const float* ihb = enc ? g_ih_enc : g_ih_dec;

        // finalizer prefetch of input-gate values (latency under the tag poll)
        float ih4[4] = {0.f, 0.f, 0.f, 0.f};
        if (fin) {
            const float* ip = ihb + (size_t)tstep * G4H + 8 * b + w;
#pragma unroll
            for (int g = 0; g < 4; g++) ih4[g] = __ldg(ip + g * HID);
        }

        // --- acquire h(sc-1): direct tag poll ---
        float hval;
        if (sc == 0) {
            hval = 0.0f;
        } else {
            const unsigned long long* sp = &g_slots[((sc - 1) & 1) * HID + tid];
            const unsigned wantTag = (unsigned)(sc - 1);
            unsigned long long v = slot_load(sp);
            while ((unsigned)(v >> 32) != wantTag) v = slot_load(sp);
            hval = __uint_as_float((unsigned)v);
        }
        hs_sh[tid] = hval;
        __syncthreads();

        // --- (Whh @ h)[grow]: 4 independent accumulators + warp reduce ---
        float s0 = 0.f, s1 = 0.f, s2 = 0.f, s3 = 0.f;
#pragma unroll
        for (int c = 0; c < 8; c++) {
            s0 = fmaf(Wreg[4*c + 0], hs_sh[l + 32 * (4*c + 0)], s0);
            s1 = fmaf(Wreg[4*c + 1], hs_sh[l + 32 * (4*c + 1)], s1);
            s2 = fmaf(Wreg[4*c + 2], hs_sh[l + 32 * (4*c + 2)], s2);
            s3 = fmaf(Wreg[4*c + 3], hs_sh[l + 32 * (4*c + 3)], s3);
        }
        float s = (s0 + s1) + (s2 + s3);
#pragma unroll
        for (int off = 16; off; off >>= 1) s += __shfl_xor_sync(0xffffffffu, s, off);
        if (l == 0) part[w] = s;

        // group barrier: the 4 warps (i,f,g,o) of element jrow
        asm volatile("bar.sync %0, 128;" :: "r"(1 + jrow) : "memory");

        // --- finalize per element (warp jj lane 0): gates, cell, publish ---
        if (fin) {
            float pi = part[w]      + ih4[0];
            float pf = part[8 + w]  + ih4[1];
            float pg = part[16 + w] + ih4[2];
            float po = part[24 + w] + ih4[3];
            float ig = sigm_f(pi);
            float fg = sigm_f(pf);
            float gg = tanh_f(pg);
            float og = sigm_f(po);
            c_reg = fg * c_reg + ig * gg;
            float h = og * tanh_f(c_reg);
            unsigned long long pv = ((unsigned long long)(unsigned)sc << 32)
                                  | (unsigned long long)__float_as_uint(h);
            slot_store(&g_slots[(sc & 1) * HID + 8 * b + w], pv);
            if (!enc) g_hs[(size_t)tstep * HID + 8 * b + w] = h;
        }
        // part[] reuse protected by next iteration's full __syncthreads
    }
}

// ---------------- launch ----------------
extern "C" void kernel_launch(void* const* d_in, const int* in_sizes, int n_in,
                              void* d_out, int out_size)
{
    const int*   seq     = (const int*)  d_in[0];
    const float* enc_emb = (const float*)d_in[1];   // [V, 512]
    const float* enc_Wih = (const float*)d_in[2];   // [4H, 512]
    const float* enc_Whh = (const float*)d_in[3];   // [4H, 1024]
    const float* enc_bih = (const float*)d_in[4];
    const float* enc_bhh = (const float*)d_in[5];
    const float* dec_emb = (const float*)d_in[6];
    const float* dec_Wih = (const float*)d_in[7];
    const float* dec_Whh = (const float*)d_in[8];
    const float* dec_bih = (const float*)d_in[9];
    const float* dec_bhh = (const float*)d_in[10];
    const float* out_W   = (const float*)d_in[11];  // [V, 1024]
    const float* out_b   = (const float*)d_in[12];
    float* out = (float*)d_out;

    float *ih_enc, *ih_dec, *hsbuf;
    cudaGetSymbolAddress((void**)&ih_enc, g_ih_enc);
    cudaGetSymbolAddress((void**)&ih_dec, g_ih_dec);
    cudaGetSymbolAddress((void**)&hsbuf,  g_hs);

    init_kernel<<<2, 1024>>>();

    // Precompute input gates: ih[t] = Wih @ emb[seq[t]] + bih + bhh   (K = EMB = 512)
    gemm_nt<<<dim3(G4H / 128, T_SEQ / 128), 256>>>(
        nullptr, enc_emb, seq, enc_Wih, enc_bih, enc_bhh, ih_enc, T_SEQ, G4H, EMB);
    gemm_nt<<<dim3(G4H / 128, (T_SEQ - 1 + 127) / 128), 256>>>(
        nullptr, dec_emb, seq, dec_Wih, dec_bih, dec_bhh, ih_dec, T_SEQ - 1, G4H, EMB);

    // Sequential encoder+decoder scan (persistent, cross-SM h exchange through L2)
    recurrence<<<NBLK, 1024>>>(enc_Whh, dec_Whh);

    // Vocab projection: logits = hs @ out_W^T + out_b  -> d_out [4095, 1, 32000]  (K = HID)
    gemm_nt<<<dim3(VOC / 128, (T_SEQ - 1 + 127) / 128), 256>>>(
        hsbuf, nullptr, nullptr, out_W, out_b, nullptr, out, T_SEQ - 1, VOC, HID);
}

// round 13
// speedup vs baseline: 1.6255x; 1.6255x over previous
#include <cuda_runtime.h>
#include <cstdint>

// Problem constants  (V,E,H,T = 32000, 512, 1024, 4096)
#define EMB    512
#define T_SEQ  4096
#define HID    1024
#define G4H    4096          // 4*HID
#define VOC    32000
#define NBLK   128           // recurrence blocks (co-resident, 1/SM)
#define NSTEPS (2*T_SEQ - 1) // 4096 encoder + 4095 decoder = 8191

// ---------------- device scratch (static: no runtime allocation) ----------------
__device__ float g_ih_enc[(size_t)T_SEQ * G4H];       // 64 MB
__device__ float g_ih_dec[(size_t)(T_SEQ-1) * G4H];   // 64 MB
__device__ float g_hs[(size_t)(T_SEQ-1) * HID];       // 16.8 MB
__device__ unsigned long long g_slots[2 * HID];       // (tag,value) pairs, double-buffered

// ---------------- single-instruction 64-bit generic accesses ----------------
__device__ __forceinline__ void slot_store(unsigned long long* p, unsigned long long v) {
    asm volatile("st.relaxed.gpu.b64 [%0], %1;" :: "l"(p), "l"(v) : "memory");
}
__device__ __forceinline__ unsigned long long slot_load(const unsigned long long* p) {
    unsigned long long v;
    asm volatile("ld.relaxed.gpu.b64 %0, [%1];" : "=l"(v) : "l"(p) : "memory");
    return v;
}

// ---------------- packed f32x2 helpers (bit-equivalence vs FFMA confirmed R1-vs-R3) ----
__device__ __forceinline__ unsigned long long pack2f(float x) {
    unsigned long long r;
    asm("mov.b64 %0, {%1, %1};" : "=l"(r) : "f"(x));
    return r;
}
__device__ __forceinline__ void ffma2(unsigned long long& d, unsigned long long a, unsigned long long b) {
    asm("fma.rn.f32x2 %0, %1, %2, %0;" : "+l"(d) : "l"(a), "l"(b));
}
__device__ __forceinline__ float lo2(unsigned long long v) { return __uint_as_float((unsigned)v); }
__device__ __forceinline__ float hi2(unsigned long long v) { return __uint_as_float((unsigned)(v >> 32)); }

// fast sigmoid/tanh via MUFU (__expf); error ~1e-6, budget 1e-3
__device__ __forceinline__ float sigm_f(float x) { return __frcp_rn(1.0f + __expf(-x)); }
__device__ __forceinline__ float tanh_f(float x) { return 2.0f * __frcp_rn(1.0f + __expf(-2.0f * x)) - 1.0f; }

// ---------------- init kernel (reset sync state each launch) ----------------
__global__ void init_kernel() {
    int i = blockIdx.x * blockDim.x + threadIdx.x;
    if (i < 2 * HID) g_slots[i] = ~0ull;   // tag never matches a real step
}

// ---------------- NT GEMM: C[M,N] = Arow(m) . B[n,:] + bias1[n] (+bias2[n]) ----
// 128x128 tile, 256 threads, 8x8 micro-tile in packed f32x2 accumulators.
// Register prefetch + smem double-buffering: ONE barrier per k-tile, LDG of
// tile k+1 and STS into the alternate buffer overlap compute on tile k.
#define BM 128
#define BN 128
#define BKT 16
#define PAD 132

__global__ __launch_bounds__(256, 2)
void gemm_nt(const float* __restrict__ A, const float* __restrict__ tab,
             const int* __restrict__ gidx, const float* __restrict__ B,
             const float* __restrict__ bias1, const float* __restrict__ bias2,
             float* __restrict__ C, int M, int N, int K)
{
    __shared__ float As[2][BKT][PAD];
    __shared__ float Bs[2][BKT][PAD];
    __shared__ int sidx[BM];

    const int tid = threadIdx.x;
    const int bm = blockIdx.y, bn = blockIdx.x;
    const int row0 = bm * BM;

    if (gidx && tid < BM) {
        int r = row0 + tid; if (r >= M) r = M - 1;
        sidx[tid] = gidx[r];
    }
    __syncthreads();

    const int tx = tid & 15, ty = tid >> 4;

    // per-thread load pointers for the two 256-thread sweeps (t=0,1)
    const float* apt[2]; const float* bpt[2];
    int arow_[2], kq_[2];
#pragma unroll
    for (int t = 0; t < 2; t++) {
        int idx  = tid + t * 256;
        int arow = idx >> 2, kq = idx & 3;
        arow_[t] = arow; kq_[t] = kq;
        int grA = row0 + arow; if (grA >= M) grA = M - 1;
        apt[t] = (gidx ? (tab + (size_t)sidx[arow] * K)
                       : (A + (size_t)grA * K)) + kq * 4;
        bpt[t] = B + (size_t)(bn * BN + arow) * K + kq * 4;
    }

    unsigned long long acc[8][4];
#pragma unroll
    for (int i = 0; i < 8; i++)
#pragma unroll
        for (int j = 0; j < 4; j++) acc[i][j] = 0ull;

    const int NT = K / BKT;
    float4 ra[2], rb[2];
#pragma unroll
    for (int t = 0; t < 2; t++) {           // prologue: LDG tile 0
        ra[t] = *(const float4*)(apt[t]);
        rb[t] = *(const float4*)(bpt[t]);
    }
#pragma unroll
    for (int t = 0; t < 2; t++) {           // STS tile 0 into buffer 0
        int arow = arow_[t], kq = kq_[t];
        As[0][kq * 4 + 0][arow] = ra[t].x; As[0][kq * 4 + 1][arow] = ra[t].y;
        As[0][kq * 4 + 2][arow] = ra[t].z; As[0][kq * 4 + 3][arow] = ra[t].w;
        Bs[0][kq * 4 + 0][arow] = rb[t].x; Bs[0][kq * 4 + 1][arow] = rb[t].y;
        Bs[0][kq * 4 + 2][arow] = rb[t].z; Bs[0][kq * 4 + 3][arow] = rb[t].w;
    }
    __syncthreads();

    for (int kt = 0; kt < NT; kt++) {
        const int cur = kt & 1, nxt = cur ^ 1;

        if (kt + 1 < NT) {                  // LDG tile kt+1 (latency under compute)
            int off = (kt + 1) * BKT;
#pragma unroll
            for (int t = 0; t < 2; t++) {
                ra[t] = *(const float4*)(apt[t] + off);
                rb[t] = *(const float4*)(bpt[t] + off);
            }
        }

#pragma unroll
        for (int kk = 0; kk < BKT; kk++) {
            float4 a0 = *(const float4*)&As[cur][kk][ty * 4];
            float4 a1 = *(const float4*)&As[cur][kk][64 + ty * 4];
            const unsigned long long* bu = (const unsigned long long*)&Bs[cur][kk][0];
            unsigned long long b0 = bu[tx * 2],      b1 = bu[tx * 2 + 1];
            unsigned long long b2 = bu[32 + tx * 2], b3 = bu[32 + tx * 2 + 1];
            float am[8] = {a0.x, a0.y, a0.z, a0.w, a1.x, a1.y, a1.z, a1.w};
#pragma unroll
            for (int i = 0; i < 8; i++) {
                unsigned long long aa = pack2f(am[i]);
                ffma2(acc[i][0], aa, b0);
                ffma2(acc[i][1], aa, b1);
                ffma2(acc[i][2], aa, b2);
                ffma2(acc[i][3], aa, b3);
            }
        }

        if (kt + 1 < NT) {                  // STS tile kt+1 into alternate buffer
#pragma unroll
            for (int t = 0; t < 2; t++) {
                int arow = arow_[t], kq = kq_[t];
                As[nxt][kq * 4 + 0][arow] = ra[t].x; As[nxt][kq * 4 + 1][arow] = ra[t].y;
                As[nxt][kq * 4 + 2][arow] = ra[t].z; As[nxt][kq * 4 + 3][arow] = ra[t].w;
                Bs[nxt][kq * 4 + 0][arow] = rb[t].x; Bs[nxt][kq * 4 + 1][arow] = rb[t].y;
                Bs[nxt][kq * 4 + 2][arow] = rb[t].z; Bs[nxt][kq * 4 + 3][arow] = rb[t].w;
            }
            __syncthreads();                // one barrier per tile
        }
    }

    // epilogue
    const int ncol0 = bn * BN + tx * 4;
    const int ncol1 = bn * BN + 64 + tx * 4;
    float bv[8];
#pragma unroll
    for (int j = 0; j < 4; j++) { bv[j] = bias1[ncol0 + j]; bv[4 + j] = bias1[ncol1 + j]; }
    if (bias2) {
#pragma unroll
        for (int j = 0; j < 4; j++) { bv[j] += bias2[ncol0 + j]; bv[4 + j] += bias2[ncol1 + j]; }
    }
#pragma unroll
    for (int i = 0; i < 8; i++) {
        int mloc = (i < 4) ? (ty * 4 + i) : (64 + ty * 4 + (i - 4));
        int m = row0 + mloc;
        if (m < M) {
            float* cp = C + (size_t)m * N;
            float4 o0, o1;
            o0.x = lo2(acc[i][0]) + bv[0]; o0.y = hi2(acc[i][0]) + bv[1];
            o0.z = lo2(acc[i][1]) + bv[2]; o0.w = hi2(acc[i][1]) + bv[3];
            o1.x = lo2(acc[i][2]) + bv[4]; o1.y = hi2(acc[i][2]) + bv[5];
            o1.z = lo2(acc[i][3]) + bv[6]; o1.w = hi2(acc[i][3]) + bv[7];
            *(float4*)(cp + ncol0) = o0;
            *(float4*)(cp + ncol1) = o1;
        }
    }
}

// ---------------- persistent recurrence kernel (R7 structure — proven fastest) ----
// Block b owns h elements [8b, 8b+8) -> 32 gate rows. Warp w = gate row:
// gi = w>>3, jj = w&7, global Whh row grow = gi*1024 + 8b + jj.
// Lane l owns columns {l, l+32, ..., l+992}; warp shuffle reduce -> part[w].
// Two full-block barriers per step (named-barrier grouping regressed 2x in R11).
// Cross-block sync: tag-polled double-buffered (tag|h) u64 slots in L2.
// Deadlock-free: tag s overwritten only at step s+2, which requires all blocks
// to have consumed tag s.

__global__ __launch_bounds__(1024, 1)
void recurrence(const float* __restrict__ encWhh, const float* __restrict__ decWhh)
{
    __shared__ float hs_sh[HID];
    __shared__ float part[32];

    const int tid = threadIdx.x;
    const int b = blockIdx.x;
    const int w = tid >> 5, l = tid & 31;
    const int gi = w >> 3, jrow = w & 7;
    const int grow = gi * HID + 8 * b + jrow;

    float Wreg[32];
    {
        const float* rp = encWhh + (size_t)grow * HID;
#pragma unroll
        for (int c = 0; c < 32; c++) Wreg[c] = __ldg(rp + l + 32 * c);
    }
    float c_reg = 0.0f;                     // cell state (tid<8 finalizers only)
    __syncthreads();

    for (int sc = 0; sc < NSTEPS; sc++) {
        if (sc == T_SEQ) {   // switch to decoder weights (registers only)
            const float* rp = decWhh + (size_t)grow * HID;
#pragma unroll
            for (int c = 0; c < 32; c++) Wreg[c] = __ldg(rp + l + 32 * c);
        }
        const bool enc = sc < T_SEQ;
        const int tstep = enc ? sc : sc - T_SEQ;
        const float* ihb = enc ? g_ih_enc : g_ih_dec;

        // prefetch input-gate values (latency hidden under the tag poll)
        float ih4[4] = {0.f, 0.f, 0.f, 0.f};
        if (tid < 8) {
            const float* ip = ihb + (size_t)tstep * G4H + 8 * b + tid;
#pragma unroll
            for (int g = 0; g < 4; g++) ih4[g] = __ldg(ip + g * HID);
        }

        // --- acquire h(sc-1): direct tag poll ---
        float hval;
        if (sc == 0) {
            hval = 0.0f;
        } else {
            const unsigned long long* sp = &g_slots[((sc - 1) & 1) * HID + tid];
            const unsigned wantTag = (unsigned)(sc - 1);
            unsigned long long v = slot_load(sp);
            while ((unsigned)(v >> 32) != wantTag) v = slot_load(sp);
            hval = __uint_as_float((unsigned)v);
        }
        hs_sh[tid] = hval;
        __syncthreads();

        // --- (Whh @ h)[grow]: 4 independent accumulators + warp reduce ---
        float s0 = 0.f, s1 = 0.f, s2 = 0.f, s3 = 0.f;
#pragma unroll
        for (int c = 0; c < 8; c++) {
            s0 = fmaf(Wreg[4*c + 0], hs_sh[l + 32 * (4*c + 0)], s0);
            s1 = fmaf(Wreg[4*c + 1], hs_sh[l + 32 * (4*c + 1)], s1);
            s2 = fmaf(Wreg[4*c + 2], hs_sh[l + 32 * (4*c + 2)], s2);
            s3 = fmaf(Wreg[4*c + 3], hs_sh[l + 32 * (4*c + 3)], s3);
        }
        float s = (s0 + s1) + (s2 + s3);
#pragma unroll
        for (int off = 16; off; off >>= 1) s += __shfl_xor_sync(0xffffffffu, s, off);
        if (l == 0) part[w] = s;
        __syncthreads();

        // --- finalize: gates, cell update, publish h ---
        if (tid < 8) {
            float pi = part[0  + tid] + ih4[0];
            float pf = part[8  + tid] + ih4[1];
            float pg = part[16 + tid] + ih4[2];
            float po = part[24 + tid] + ih4[3];
            float ig = sigm_f(pi);
            float fg = sigm_f(pf);
            float gg = tanh_f(pg);
            float og = sigm_f(po);
            c_reg = fg * c_reg + ig * gg;
            float h = og * tanh_f(c_reg);
            unsigned long long pv = ((unsigned long long)(unsigned)sc << 32)
                                  | (unsigned long long)__float_as_uint(h);
            slot_store(&g_slots[(sc & 1) * HID + 8 * b + tid], pv);
            if (!enc) g_hs[(size_t)tstep * HID + 8 * b + tid] = h;
        }
        // next iteration's poll + barrier protect hs_sh/part reuse
    }
}

// ---------------- launch ----------------
extern "C" void kernel_launch(void* const* d_in, const int* in_sizes, int n_in,
                              void* d_out, int out_size)
{
    const int*   seq     = (const int*)  d_in[0];
    const float* enc_emb = (const float*)d_in[1];   // [V, 512]
    const float* enc_Wih = (const float*)d_in[2];   // [4H, 512]
    const float* enc_Whh = (const float*)d_in[3];   // [4H, 1024]
    const float* enc_bih = (const float*)d_in[4];
    const float* enc_bhh = (const float*)d_in[5];
    const float* dec_emb = (const float*)d_in[6];
    const float* dec_Wih = (const float*)d_in[7];
    const float* dec_Whh = (const float*)d_in[8];
    const float* dec_bih = (const float*)d_in[9];
    const float* dec_bhh = (const float*)d_in[10];
    const float* out_W   = (const float*)d_in[11];  // [V, 1024]
    const float* out_b   = (const float*)d_in[12];
    float* out = (float*)d_out;

    float *ih_enc, *ih_dec, *hsbuf;
    cudaGetSymbolAddress((void**)&ih_enc, g_ih_enc);
    cudaGetSymbolAddress((void**)&ih_dec, g_ih_dec);
    cudaGetSymbolAddress((void**)&hsbuf,  g_hs);

    init_kernel<<<2, 1024>>>();

    // Precompute input gates: ih[t] = Wih @ emb[seq[t]] + bih + bhh   (K = EMB = 512)
    gemm_nt<<<dim3(G4H / 128, T_SEQ / 128), 256>>>(
        nullptr, enc_emb, seq, enc_Wih, enc_bih, enc_bhh, ih_enc, T_SEQ, G4H, EMB);
    gemm_nt<<<dim3(G4H / 128, (T_SEQ - 1 + 127) / 128), 256>>>(
        nullptr, dec_emb, seq, dec_Wih, dec_bih, dec_bhh, ih_dec, T_SEQ - 1, G4H, EMB);

    // Sequential encoder+decoder scan (persistent, cross-SM h exchange through L2)
    recurrence<<<NBLK, 1024>>>(enc_Whh, dec_Whh);

    // Vocab projection: logits = hs @ out_W^T + out_b  -> d_out [4095, 1, 32000]  (K = HID)
    gemm_nt<<<dim3(VOC / 128, (T_SEQ - 1 + 127) / 128), 256>>>(
        hsbuf, nullptr, nullptr, out_W, out_b, nullptr, out, T_SEQ - 1, VOC, HID);
}

// round 15
// speedup vs baseline: 1.8428x; 1.1337x over previous
#include <cuda_runtime.h>
#include <cuda_bf16.h>
#include <cstdint>

// Problem constants  (V,E,H,T = 32000, 512, 1024, 4096)
#define EMB    512
#define T_SEQ  4096
#define HID    1024
#define G4H    4096          // 4*HID
#define VOC    32000
#define NBLK   128           // recurrence blocks (co-resident, 1/SM)
#define NSTEPS (2*T_SEQ - 1) // 4096 encoder + 4095 decoder = 8191
#define MROWS  4096          // padded hs rows for projection (4095 real + 1 zero)

// ---------------- device scratch (static: no runtime allocation) ----------------
__device__ float g_ih_enc[(size_t)T_SEQ * G4H];       // 64 MB
__device__ float g_ih_dec[(size_t)(T_SEQ-1) * G4H];   // 64 MB
__device__ float g_hs[(size_t)(T_SEQ-1) * HID];       // 16.8 MB
__device__ unsigned long long g_slots[2 * HID];       // (tag,value) pairs, double-buffered
__device__ __align__(256) __nv_bfloat16 g_hs_hi[(size_t)MROWS * HID];   // 8 MB
__device__ __align__(256) __nv_bfloat16 g_hs_lo[(size_t)MROWS * HID];   // 8 MB
__device__ __align__(256) __nv_bfloat16 g_w_hi[(size_t)VOC * HID];      // 64 MB
__device__ __align__(256) __nv_bfloat16 g_w_lo[(size_t)VOC * HID];      // 64 MB

// ---------------- single-instruction 64-bit generic accesses ----------------
__device__ __forceinline__ void slot_store(unsigned long long* p, unsigned long long v) {
    asm volatile("st.relaxed.gpu.b64 [%0], %1;" :: "l"(p), "l"(v) : "memory");
}
__device__ __forceinline__ unsigned long long slot_load(const unsigned long long* p) {
    unsigned long long v;
    asm volatile("ld.relaxed.gpu.b64 %0, [%1];" : "=l"(v) : "l"(p) : "memory");
    return v;
}

// ---------------- packed f32x2 helpers ----------------
__device__ __forceinline__ unsigned long long pack2f(float x) {
    unsigned long long r;
    asm("mov.b64 %0, {%1, %1};" : "=l"(r) : "f"(x));
    return r;
}
__device__ __forceinline__ void ffma2(unsigned long long& d, unsigned long long a, unsigned long long b) {
    asm("fma.rn.f32x2 %0, %1, %2, %0;" : "+l"(d) : "l"(a), "l"(b));
}
__device__ __forceinline__ float lo2(unsigned long long v) { return __uint_as_float((unsigned)v); }
__device__ __forceinline__ float hi2(unsigned long long v) { return __uint_as_float((unsigned)(v >> 32)); }

// fast sigmoid/tanh via MUFU
__device__ __forceinline__ float sigm_f(float x) { return __frcp_rn(1.0f + __expf(-x)); }
__device__ __forceinline__ float tanh_f(float x) { return 2.0f * __frcp_rn(1.0f + __expf(-2.0f * x)) - 1.0f; }

// ---------------- Ampere-style bf16 tensor mma (baseline sm_80+, works on sm_103) ----
// D(16x8,f32) += A(16x16 bf16 row-major) * B(16x8 bf16 col-major)
__device__ __forceinline__ void mma16816(float c[4], const unsigned a[4], const unsigned b[2]) {
    asm volatile(
        "mma.sync.aligned.m16n8k16.row.col.f32.bf16.bf16.f32 "
        "{%0,%1,%2,%3}, {%4,%5,%6,%7}, {%8,%9}, {%0,%1,%2,%3};"
        : "+f"(c[0]), "+f"(c[1]), "+f"(c[2]), "+f"(c[3])
        : "r"(a[0]), "r"(a[1]), "r"(a[2]), "r"(a[3]), "r"(b[0]), "r"(b[1]));
}

// ---------------- init kernel ----------------
__global__ void init_kernel() {
    int i = blockIdx.x * blockDim.x + threadIdx.x;
    if (i < 2 * HID) g_slots[i] = ~0ull;
}

// ---------------- fp32 -> bf16 hi/lo split ----------------
__global__ void conv_split(const float* __restrict__ src, __nv_bfloat16* __restrict__ hi,
                           __nv_bfloat16* __restrict__ lo, size_t n, size_t srcN)
{
    size_t i = (size_t)blockIdx.x * blockDim.x + threadIdx.x;
    if (i >= n) return;
    float x = (i < srcN) ? src[i] : 0.0f;
    __nv_bfloat16 h = __float2bfloat16(x);
    hi[i] = h;
    lo[i] = __float2bfloat16(x - __bfloat162float(h));
}

// ---------------- NT GEMM (SIMT f32x2) for ih gates — R13 unchanged ----------------
#define BM 128
#define BN 128
#define BKT 16
#define PAD 132

__global__ __launch_bounds__(256, 2)
void gemm_nt(const float* __restrict__ A, const float* __restrict__ tab,
             const int* __restrict__ gidx, const float* __restrict__ B,
             const float* __restrict__ bias1, const float* __restrict__ bias2,
             float* __restrict__ C, int M, int N, int K)
{
    __shared__ float As[2][BKT][PAD];
    __shared__ float Bs[2][BKT][PAD];
    __shared__ int sidx[BM];

    const int tid = threadIdx.x;
    const int bm = blockIdx.y, bn = blockIdx.x;
    const int row0 = bm * BM;

    if (gidx && tid < BM) {
        int r = row0 + tid; if (r >= M) r = M - 1;
        sidx[tid] = gidx[r];
    }
    __syncthreads();

    const int tx = tid & 15, ty = tid >> 4;

    const float* apt[2]; const float* bpt[2];
    int arow_[2], kq_[2];
#pragma unroll
    for (int t = 0; t < 2; t++) {
        int idx  = tid + t * 256;
        int arow = idx >> 2, kq = idx & 3;
        arow_[t] = arow; kq_[t] = kq;
        int grA = row0 + arow; if (grA >= M) grA = M - 1;
        apt[t] = (gidx ? (tab + (size_t)sidx[arow] * K)
                       : (A + (size_t)grA * K)) + kq * 4;
        bpt[t] = B + (size_t)(bn * BN + arow) * K + kq * 4;
    }

    unsigned long long acc[8][4];
#pragma unroll
    for (int i = 0; i < 8; i++)
#pragma unroll
        for (int j = 0; j < 4; j++) acc[i][j] = 0ull;

    const int NT = K / BKT;
    float4 ra[2], rb[2];
#pragma unroll
    for (int t = 0; t < 2; t++) {
        ra[t] = *(const float4*)(apt[t]);
        rb[t] = *(const float4*)(bpt[t]);
    }
#pragma unroll
    for (int t = 0; t < 2; t++) {
        int arow = arow_[t], kq = kq_[t];
        As[0][kq * 4 + 0][arow] = ra[t].x; As[0][kq * 4 + 1][arow] = ra[t].y;
        As[0][kq * 4 + 2][arow] = ra[t].z; As[0][kq * 4 + 3][arow] = ra[t].w;
        Bs[0][kq * 4 + 0][arow] = rb[t].x; Bs[0][kq * 4 + 1][arow] = rb[t].y;
        Bs[0][kq * 4 + 2][arow] = rb[t].z; Bs[0][kq * 4 + 3][arow] = rb[t].w;
    }
    __syncthreads();

    for (int kt = 0; kt < NT; kt++) {
        const int cur = kt & 1, nxt = cur ^ 1;

        if (kt + 1 < NT) {
            int off = (kt + 1) * BKT;
#pragma unroll
            for (int t = 0; t < 2; t++) {
                ra[t] = *(const float4*)(apt[t] + off);
                rb[t] = *(const float4*)(bpt[t] + off);
            }
        }

#pragma unroll
        for (int kk = 0; kk < BKT; kk++) {
            float4 a0 = *(const float4*)&As[cur][kk][ty * 4];
            float4 a1 = *(const float4*)&As[cur][kk][64 + ty * 4];
            const unsigned long long* bu = (const unsigned long long*)&Bs[cur][kk][0];
            unsigned long long b0 = bu[tx * 2],      b1 = bu[tx * 2 + 1];
            unsigned long long b2 = bu[32 + tx * 2], b3 = bu[32 + tx * 2 + 1];
            float am[8] = {a0.x, a0.y, a0.z, a0.w, a1.x, a1.y, a1.z, a1.w};
#pragma unroll
            for (int i = 0; i < 8; i++) {
                unsigned long long aa = pack2f(am[i]);
                ffma2(acc[i][0], aa, b0);
                ffma2(acc[i][1], aa, b1);
                ffma2(acc[i][2], aa, b2);
                ffma2(acc[i][3], aa, b3);
            }
        }

        if (kt + 1 < NT) {
#pragma unroll
            for (int t = 0; t < 2; t++) {
                int arow = arow_[t], kq = kq_[t];
                As[nxt][kq * 4 + 0][arow] = ra[t].x; As[nxt][kq * 4 + 1][arow] = ra[t].y;
                As[nxt][kq * 4 + 2][arow] = ra[t].z; As[nxt][kq * 4 + 3][arow] = ra[t].w;
                Bs[nxt][kq * 4 + 0][arow] = rb[t].x; Bs[nxt][kq * 4 + 1][arow] = rb[t].y;
                Bs[nxt][kq * 4 + 2][arow] = rb[t].z; Bs[nxt][kq * 4 + 3][arow] = rb[t].w;
            }
            __syncthreads();
        }
    }

    const int ncol0 = bn * BN + tx * 4;
    const int ncol1 = bn * BN + 64 + tx * 4;
    float bv[8];
#pragma unroll
    for (int j = 0; j < 4; j++) { bv[j] = bias1[ncol0 + j]; bv[4 + j] = bias1[ncol1 + j]; }
    if (bias2) {
#pragma unroll
        for (int j = 0; j < 4; j++) { bv[j] += bias2[ncol0 + j]; bv[4 + j] += bias2[ncol1 + j]; }
    }
#pragma unroll
    for (int i = 0; i < 8; i++) {
        int mloc = (i < 4) ? (ty * 4 + i) : (64 + ty * 4 + (i - 4));
        int m = row0 + mloc;
        if (m < M) {
            float* cp = C + (size_t)m * N;
            float4 o0, o1;
            o0.x = lo2(acc[i][0]) + bv[0]; o0.y = hi2(acc[i][0]) + bv[1];
            o0.z = lo2(acc[i][1]) + bv[2]; o0.w = hi2(acc[i][1]) + bv[3];
            o1.x = lo2(acc[i][2]) + bv[4]; o1.y = hi2(acc[i][2]) + bv[5];
            o1.z = lo2(acc[i][3]) + bv[6]; o1.w = hi2(acc[i][3]) + bv[7];
            *(float4*)(cp + ncol0) = o0;
            *(float4*)(cp + ncol1) = o1;
        }
    }
}

// ---------------- persistent recurrence kernel (R13, unchanged) ----------------
__global__ __launch_bounds__(1024, 1)
void recurrence(const float* __restrict__ encWhh, const float* __restrict__ decWhh)
{
    __shared__ float hs_sh[HID];
    __shared__ float part[32];

    const int tid = threadIdx.x;
    const int b = blockIdx.x;
    const int w = tid >> 5, l = tid & 31;
    const int gi = w >> 3, jrow = w & 7;
    const int grow = gi * HID + 8 * b + jrow;

    float Wreg[32];
    {
        const float* rp = encWhh + (size_t)grow * HID;
#pragma unroll
        for (int c = 0; c < 32; c++) Wreg[c] = __ldg(rp + l + 32 * c);
    }
    float c_reg = 0.0f;
    __syncthreads();

    for (int sc = 0; sc < NSTEPS; sc++) {
        if (sc == T_SEQ) {
            const float* rp = decWhh + (size_t)grow * HID;
#pragma unroll
            for (int c = 0; c < 32; c++) Wreg[c] = __ldg(rp + l + 32 * c);
        }
        const bool enc = sc < T_SEQ;
        const int tstep = enc ? sc : sc - T_SEQ;
        const float* ihb = enc ? g_ih_enc : g_ih_dec;

        float ih4[4] = {0.f, 0.f, 0.f, 0.f};
        if (tid < 8) {
            const float* ip = ihb + (size_t)tstep * G4H + 8 * b + tid;
#pragma unroll
            for (int g = 0; g < 4; g++) ih4[g] = __ldg(ip + g * HID);
        }

        float hval;
        if (sc == 0) {
            hval = 0.0f;
        } else {
            const unsigned long long* sp = &g_slots[((sc - 1) & 1) * HID + tid];
            const unsigned wantTag = (unsigned)(sc - 1);
            unsigned long long v = slot_load(sp);
            while ((unsigned)(v >> 32) != wantTag) v = slot_load(sp);
            hval = __uint_as_float((unsigned)v);
        }
        hs_sh[tid] = hval;
        __syncthreads();

        float s0 = 0.f, s1 = 0.f, s2 = 0.f, s3 = 0.f;
#pragma unroll
        for (int c = 0; c < 8; c++) {
            s0 = fmaf(Wreg[4*c + 0], hs_sh[l + 32 * (4*c + 0)], s0);
            s1 = fmaf(Wreg[4*c + 1], hs_sh[l + 32 * (4*c + 1)], s1);
            s2 = fmaf(Wreg[4*c + 2], hs_sh[l + 32 * (4*c + 2)], s2);
            s3 = fmaf(Wreg[4*c + 3], hs_sh[l + 32 * (4*c + 3)], s3);
        }
        float s = (s0 + s1) + (s2 + s3);
#pragma unroll
        for (int off = 16; off; off >>= 1) s += __shfl_xor_sync(0xffffffffu, s, off);
        if (l == 0) part[w] = s;
        __syncthreads();

        if (tid < 8) {
            float pi = part[0  + tid] + ih4[0];
            float pf = part[8  + tid] + ih4[1];
            float pg = part[16 + tid] + ih4[2];
            float po = part[24 + tid] + ih4[3];
            float ig = sigm_f(pi);
            float fg = sigm_f(pf);
            float gg = tanh_f(pg);
            float og = sigm_f(po);
            c_reg = fg * c_reg + ig * gg;
            float h = og * tanh_f(c_reg);
            unsigned long long pv = ((unsigned long long)(unsigned)sc << 32)
                                  | (unsigned long long)__float_as_uint(h);
            slot_store(&g_slots[(sc & 1) * HID + 8 * b + tid], pv);
            if (!enc) g_hs[(size_t)tstep * HID + 8 * b + tid] = h;
        }
    }
}

// ---------------- tensor-core projection via mma.sync (bf16 hi/lo, 3 passes) ----
// out[m, n] = hs[m] . W[n] + b[n].  A = hs (row-major), B = W (row-major over n
// == col-major kxn, exactly mma's row.col form). 128x128 CTA tile, 8 warps in
// 2(m) x 4(n); warp tile 64x32 = 4 x 4 mma tiles of 16x8. K in 16 chunks of 64.
// Smem rows stride 144B (bank-conflict-free fragment LDS, stride = 4 mod 32 banks).
#define PJ_STRIDE 144
#define PJ_OPBYTES (128 * PJ_STRIDE)            // 18432 per operand
#define PJ_SMEM    (4 * PJ_OPBYTES)             // 73728

__global__ __launch_bounds__(256, 2)
void proj_mma(const float* __restrict__ bias, float* __restrict__ out)
{
    extern __shared__ char smc[];
    char* sAhi = smc;
    char* sAlo = smc + PJ_OPBYTES;
    char* sBhi = smc + 2 * PJ_OPBYTES;
    char* sBlo = smc + 3 * PJ_OPBYTES;

    const int tid = threadIdx.x;
    const int wid = tid >> 5, lane = tid & 31;
    const int g8 = lane >> 2, tg = lane & 3;
    const int wm = wid & 1, wn = wid >> 1;       // warp grid 2(m) x 4(n)
    const int n0 = blockIdx.x * 128;             // vocab tile
    const int m0 = blockIdx.y * 128;             // hs-row tile

    const char* gA_hi = (const char*)(g_hs_hi + (size_t)m0 * HID);
    const char* gA_lo = (const char*)(g_hs_lo + (size_t)m0 * HID);
    const char* gB_hi = (const char*)(g_w_hi + (size_t)n0 * HID);
    const char* gB_lo = (const char*)(g_w_lo + (size_t)n0 * HID);

    float c[4][4][4];
#pragma unroll
    for (int i = 0; i < 4; i++)
#pragma unroll
        for (int j = 0; j < 4; j++)
#pragma unroll
            for (int k = 0; k < 4; k++) c[i][j][k] = 0.0f;

    for (int ch = 0; ch < 16; ch++) {
        const int kbyte = ch * 128;              // 64 bf16 = 128 bytes per row
        // stage 4 operands: 128 rows x 128B each, 256 threads x 4 x uint4
#pragma unroll
        for (int it = 0; it < 4; it++) {
            int g = tid + it * 256;              // 0..1023
            int row = g >> 3, gr = g & 7;
            size_t go = (size_t)row * (HID * 2) + kbyte + gr * 16;
            int so = row * PJ_STRIDE + gr * 16;
            *(uint4*)(sAhi + so) = *(const uint4*)(gA_hi + go);
            *(uint4*)(sAlo + so) = *(const uint4*)(gA_lo + go);
            *(uint4*)(sBhi + so) = *(const uint4*)(gB_hi + go);
            *(uint4*)(sBlo + so) = *(const uint4*)(gB_lo + go);
        }
        __syncthreads();

#pragma unroll
        for (int ks = 0; ks < 4; ks++) {
            // B fragments for 4 n-tiles (hi+lo)
            unsigned bhi[4][2], blo[4][2];
#pragma unroll
            for (int nt = 0; nt < 4; nt++) {
                int o = (wn * 32 + nt * 8 + g8) * PJ_STRIDE + ks * 32 + tg * 4;
                bhi[nt][0] = *(const unsigned*)(sBhi + o);
                bhi[nt][1] = *(const unsigned*)(sBhi + o + 16);
                blo[nt][0] = *(const unsigned*)(sBlo + o);
                blo[nt][1] = *(const unsigned*)(sBlo + o + 16);
            }
#pragma unroll
            for (int mt = 0; mt < 4; mt++) {
                int o = (wm * 64 + mt * 16 + g8) * PJ_STRIDE + ks * 32 + tg * 4;
                unsigned ahi[4], alo[4];
                ahi[0] = *(const unsigned*)(sAhi + o);
                ahi[1] = *(const unsigned*)(sAhi + o + 8 * PJ_STRIDE);
                ahi[2] = *(const unsigned*)(sAhi + o + 16);
                ahi[3] = *(const unsigned*)(sAhi + o + 8 * PJ_STRIDE + 16);
                alo[0] = *(const unsigned*)(sAlo + o);
                alo[1] = *(const unsigned*)(sAlo + o + 8 * PJ_STRIDE);
                alo[2] = *(const unsigned*)(sAlo + o + 16);
                alo[3] = *(const unsigned*)(sAlo + o + 8 * PJ_STRIDE + 16);
#pragma unroll
                for (int nt = 0; nt < 4; nt++) {
                    mma16816(c[mt][nt], ahi, bhi[nt]);   // hi*hi
                    mma16816(c[mt][nt], ahi, blo[nt]);   // hi*lo
                    mma16816(c[mt][nt], alo, bhi[nt]);   // lo*hi
                }
            }
        }
        __syncthreads();
    }

    // epilogue: c0,c1 -> (row, col..col+1); c2,c3 -> (row+8, ...)
#pragma unroll
    for (int mt = 0; mt < 4; mt++) {
        int row = m0 + wm * 64 + mt * 16 + g8;
#pragma unroll
        for (int nt = 0; nt < 4; nt++) {
            int col = n0 + wn * 32 + nt * 8 + tg * 2;
            float b0 = __ldg(bias + col), b1 = __ldg(bias + col + 1);
            if (row < T_SEQ - 1) {
                float2 o; o.x = c[mt][nt][0] + b0; o.y = c[mt][nt][1] + b1;
                *(float2*)(out + (size_t)row * VOC + col) = o;
            }
            if (row + 8 < T_SEQ - 1) {
                float2 o; o.x = c[mt][nt][2] + b0; o.y = c[mt][nt][3] + b1;
                *(float2*)(out + (size_t)(row + 8) * VOC + col) = o;
            }
        }
    }
}

// ---------------- launch ----------------
extern "C" void kernel_launch(void* const* d_in, const int* in_sizes, int n_in,
                              void* d_out, int out_size)
{
    const int*   seq     = (const int*)  d_in[0];
    const float* enc_emb = (const float*)d_in[1];   // [V, 512]
    const float* enc_Wih = (const float*)d_in[2];   // [4H, 512]
    const float* enc_Whh = (const float*)d_in[3];   // [4H, 1024]
    const float* enc_bih = (const float*)d_in[4];
    const float* enc_bhh = (const float*)d_in[5];
    const float* dec_emb = (const float*)d_in[6];
    const float* dec_Wih = (const float*)d_in[7];
    const float* dec_Whh = (const float*)d_in[8];
    const float* dec_bih = (const float*)d_in[9];
    const float* dec_bhh = (const float*)d_in[10];
    const float* out_W   = (const float*)d_in[11];  // [V, 1024]
    const float* out_b   = (const float*)d_in[12];
    float* out = (float*)d_out;

    float *ih_enc, *ih_dec, *hsbuf;
    __nv_bfloat16 *hshi, *hslo, *whi, *wlo;
    cudaGetSymbolAddress((void**)&ih_enc, g_ih_enc);
    cudaGetSymbolAddress((void**)&ih_dec, g_ih_dec);
    cudaGetSymbolAddress((void**)&hsbuf,  g_hs);
    cudaGetSymbolAddress((void**)&hshi,   g_hs_hi);
    cudaGetSymbolAddress((void**)&hslo,   g_hs_lo);
    cudaGetSymbolAddress((void**)&whi,    g_w_hi);
    cudaGetSymbolAddress((void**)&wlo,    g_w_lo);

    init_kernel<<<2, 1024>>>();

    // out_W -> bf16 hi/lo (independent of recurrence)
    {
        size_t n = (size_t)VOC * HID;
        conv_split<<<(unsigned)((n + 255) / 256), 256>>>(out_W, whi, wlo, n, n);
    }

    // Precompute input gates (K = EMB = 512)
    gemm_nt<<<dim3(G4H / 128, T_SEQ / 128), 256>>>(
        nullptr, enc_emb, seq, enc_Wih, enc_bih, enc_bhh, ih_enc, T_SEQ, G4H, EMB);
    gemm_nt<<<dim3(G4H / 128, (T_SEQ - 1 + 127) / 128), 256>>>(
        nullptr, dec_emb, seq, dec_Wih, dec_bih, dec_bhh, ih_dec, T_SEQ - 1, G4H, EMB);

    // Sequential encoder+decoder scan
    recurrence<<<NBLK, 1024>>>(enc_Whh, dec_Whh);

    // hs -> bf16 hi/lo (row 4095 zero-padded)
    {
        size_t n = (size_t)MROWS * HID, sn = (size_t)(T_SEQ - 1) * HID;
        conv_split<<<(unsigned)((n + 255) / 256), 256>>>(hsbuf, hshi, hslo, n, sn);
    }

    // Tensor-core projection: [4095, 32000] via mma.sync bf16 hi/lo
    cudaFuncSetAttribute(proj_mma, cudaFuncAttributeMaxDynamicSharedMemorySize, PJ_SMEM);
    proj_mma<<<dim3(VOC / 128, MROWS / 128), 256, PJ_SMEM>>>(out_b, out);
}

// round 16
// speedup vs baseline: 1.8910x; 1.0261x over previous
#include <cuda_runtime.h>
#include <cuda_bf16.h>
#include <cstdint>

// Problem constants  (V,E,H,T = 32000, 512, 1024, 4096)
#define EMB    512
#define T_SEQ  4096
#define HID    1024
#define G4H    4096          // 4*HID
#define VOC    32000
#define NBLK   128           // recurrence blocks (co-resident, 1/SM)
#define NSTEPS (2*T_SEQ - 1) // 4096 encoder + 4095 decoder = 8191
#define MROWS  4096          // padded hs rows for projection (4095 real + 1 zero)

// ---------------- device scratch (static: no runtime allocation) ----------------
__device__ float g_ih_enc[(size_t)T_SEQ * G4H];       // 64 MB
__device__ float g_ih_dec[(size_t)(T_SEQ-1) * G4H];   // 64 MB
__device__ float g_hs[(size_t)(T_SEQ-1) * HID];       // 16.8 MB
__device__ unsigned long long g_slots[2 * HID];       // (tag,value) pairs, double-buffered
__device__ __align__(256) __nv_bfloat16 g_hs_hi[(size_t)MROWS * HID];   // 8 MB
__device__ __align__(256) __nv_bfloat16 g_hs_lo[(size_t)MROWS * HID];   // 8 MB
__device__ __align__(256) __nv_bfloat16 g_w_hi[(size_t)VOC * HID];      // 64 MB
__device__ __align__(256) __nv_bfloat16 g_w_lo[(size_t)VOC * HID];      // 64 MB

// ---------------- single-instruction 64-bit generic accesses ----------------
__device__ __forceinline__ void slot_store(unsigned long long* p, unsigned long long v) {
    asm volatile("st.relaxed.gpu.b64 [%0], %1;" :: "l"(p), "l"(v) : "memory");
}
__device__ __forceinline__ unsigned long long slot_load(const unsigned long long* p) {
    unsigned long long v;
    asm volatile("ld.relaxed.gpu.b64 %0, [%1];" : "=l"(v) : "l"(p) : "memory");
    return v;
}

// ---------------- packed f32x2 helpers ----------------
__device__ __forceinline__ unsigned long long pack2f(float x) {
    unsigned long long r;
    asm("mov.b64 %0, {%1, %1};" : "=l"(r) : "f"(x));
    return r;
}
__device__ __forceinline__ void ffma2(unsigned long long& d, unsigned long long a, unsigned long long b) {
    asm("fma.rn.f32x2 %0, %1, %2, %0;" : "+l"(d) : "l"(a), "l"(b));
}
__device__ __forceinline__ float lo2(unsigned long long v) { return __uint_as_float((unsigned)v); }
__device__ __forceinline__ float hi2(unsigned long long v) { return __uint_as_float((unsigned)(v >> 32)); }

// fast sigmoid/tanh via MUFU
__device__ __forceinline__ float sigm_f(float x) { return __frcp_rn(1.0f + __expf(-x)); }
__device__ __forceinline__ float tanh_f(float x) { return 2.0f * __frcp_rn(1.0f + __expf(-2.0f * x)) - 1.0f; }

// ---------------- Ampere-style bf16 tensor mma (baseline sm_80+, works on sm_103) ----
__device__ __forceinline__ void mma16816(float c[4], const unsigned a[4], const unsigned b[2]) {
    asm volatile(
        "mma.sync.aligned.m16n8k16.row.col.f32.bf16.bf16.f32 "
        "{%0,%1,%2,%3}, {%4,%5,%6,%7}, {%8,%9}, {%0,%1,%2,%3};"
        : "+f"(c[0]), "+f"(c[1]), "+f"(c[2]), "+f"(c[3])
        : "r"(a[0]), "r"(a[1]), "r"(a[2]), "r"(a[3]), "r"(b[0]), "r"(b[1]));
}

// ---------------- init kernel ----------------
__global__ void init_kernel() {
    int i = blockIdx.x * blockDim.x + threadIdx.x;
    if (i < 2 * HID) g_slots[i] = ~0ull;
}

// ---------------- fp32 -> bf16 hi/lo split ----------------
__global__ void conv_split(const float* __restrict__ src, __nv_bfloat16* __restrict__ hi,
                           __nv_bfloat16* __restrict__ lo, size_t n, size_t srcN)
{
    size_t i = (size_t)blockIdx.x * blockDim.x + threadIdx.x;
    if (i >= n) return;
    float x = (i < srcN) ? src[i] : 0.0f;
    __nv_bfloat16 h = __float2bfloat16(x);
    hi[i] = h;
    lo[i] = __float2bfloat16(x - __bfloat162float(h));
}

// ---------------- NT GEMM (SIMT f32x2) for ih gates — R13 unchanged ----------------
#define BM 128
#define BN 128
#define BKT 16
#define PAD 132

__global__ __launch_bounds__(256, 2)
void gemm_nt(const float* __restrict__ A, const float* __restrict__ tab,
             const int* __restrict__ gidx, const float* __restrict__ B,
             const float* __restrict__ bias1, const float* __restrict__ bias2,
             float* __restrict__ C, int M, int N, int K)
{
    __shared__ float As[2][BKT][PAD];
    __shared__ float Bs[2][BKT][PAD];
    __shared__ int sidx[BM];

    const int tid = threadIdx.x;
    const int bm = blockIdx.y, bn = blockIdx.x;
    const int row0 = bm * BM;

    if (gidx && tid < BM) {
        int r = row0 + tid; if (r >= M) r = M - 1;
        sidx[tid] = gidx[r];
    }
    __syncthreads();

    const int tx = tid & 15, ty = tid >> 4;

    const float* apt[2]; const float* bpt[2];
    int arow_[2], kq_[2];
#pragma unroll
    for (int t = 0; t < 2; t++) {
        int idx  = tid + t * 256;
        int arow = idx >> 2, kq = idx & 3;
        arow_[t] = arow; kq_[t] = kq;
        int grA = row0 + arow; if (grA >= M) grA = M - 1;
        apt[t] = (gidx ? (tab + (size_t)sidx[arow] * K)
                       : (A + (size_t)grA * K)) + kq * 4;
        bpt[t] = B + (size_t)(bn * BN + arow) * K + kq * 4;
    }

    unsigned long long acc[8][4];
#pragma unroll
    for (int i = 0; i < 8; i++)
#pragma unroll
        for (int j = 0; j < 4; j++) acc[i][j] = 0ull;

    const int NT = K / BKT;
    float4 ra[2], rb[2];
#pragma unroll
    for (int t = 0; t < 2; t++) {
        ra[t] = *(const float4*)(apt[t]);
        rb[t] = *(const float4*)(bpt[t]);
    }
#pragma unroll
    for (int t = 0; t < 2; t++) {
        int arow = arow_[t], kq = kq_[t];
        As[0][kq * 4 + 0][arow] = ra[t].x; As[0][kq * 4 + 1][arow] = ra[t].y;
        As[0][kq * 4 + 2][arow] = ra[t].z; As[0][kq * 4 + 3][arow] = ra[t].w;
        Bs[0][kq * 4 + 0][arow] = rb[t].x; Bs[0][kq * 4 + 1][arow] = rb[t].y;
        Bs[0][kq * 4 + 2][arow] = rb[t].z; Bs[0][kq * 4 + 3][arow] = rb[t].w;
    }
    __syncthreads();

    for (int kt = 0; kt < NT; kt++) {
        const int cur = kt & 1, nxt = cur ^ 1;

        if (kt + 1 < NT) {
            int off = (kt + 1) * BKT;
#pragma unroll
            for (int t = 0; t < 2; t++) {
                ra[t] = *(const float4*)(apt[t] + off);
                rb[t] = *(const float4*)(bpt[t] + off);
            }
        }

#pragma unroll
        for (int kk = 0; kk < BKT; kk++) {
            float4 a0 = *(const float4*)&As[cur][kk][ty * 4];
            float4 a1 = *(const float4*)&As[cur][kk][64 + ty * 4];
            const unsigned long long* bu = (const unsigned long long*)&Bs[cur][kk][0];
            unsigned long long b0 = bu[tx * 2],      b1 = bu[tx * 2 + 1];
            unsigned long long b2 = bu[32 + tx * 2], b3 = bu[32 + tx * 2 + 1];
            float am[8] = {a0.x, a0.y, a0.z, a0.w, a1.x, a1.y, a1.z, a1.w};
#pragma unroll
            for (int i = 0; i < 8; i++) {
                unsigned long long aa = pack2f(am[i]);
                ffma2(acc[i][0], aa, b0);
                ffma2(acc[i][1], aa, b1);
                ffma2(acc[i][2], aa, b2);
                ffma2(acc[i][3], aa, b3);
            }
        }

        if (kt + 1 < NT) {
#pragma unroll
            for (int t = 0; t < 2; t++) {
                int arow = arow_[t], kq = kq_[t];
                As[nxt][kq * 4 + 0][arow] = ra[t].x; As[nxt][kq * 4 + 1][arow] = ra[t].y;
                As[nxt][kq * 4 + 2][arow] = ra[t].z; As[nxt][kq * 4 + 3][arow] = ra[t].w;
                Bs[nxt][kq * 4 + 0][arow] = rb[t].x; Bs[nxt][kq * 4 + 1][arow] = rb[t].y;
                Bs[nxt][kq * 4 + 2][arow] = rb[t].z; Bs[nxt][kq * 4 + 3][arow] = rb[t].w;
            }
            __syncthreads();
        }
    }

    const int ncol0 = bn * BN + tx * 4;
    const int ncol1 = bn * BN + 64 + tx * 4;
    float bv[8];
#pragma unroll
    for (int j = 0; j < 4; j++) { bv[j] = bias1[ncol0 + j]; bv[4 + j] = bias1[ncol1 + j]; }
    if (bias2) {
#pragma unroll
        for (int j = 0; j < 4; j++) { bv[j] += bias2[ncol0 + j]; bv[4 + j] += bias2[ncol1 + j]; }
    }
#pragma unroll
    for (int i = 0; i < 8; i++) {
        int mloc = (i < 4) ? (ty * 4 + i) : (64 + ty * 4 + (i - 4));
        int m = row0 + mloc;
        if (m < M) {
            float* cp = C + (size_t)m * N;
            float4 o0, o1;
            o0.x = lo2(acc[i][0]) + bv[0]; o0.y = hi2(acc[i][0]) + bv[1];
            o0.z = lo2(acc[i][1]) + bv[2]; o0.w = hi2(acc[i][1]) + bv[3];
            o1.x = lo2(acc[i][2]) + bv[4]; o1.y = hi2(acc[i][2]) + bv[5];
            o1.z = lo2(acc[i][3]) + bv[6]; o1.w = hi2(acc[i][3]) + bv[7];
            *(float4*)(cp + ncol0) = o0;
            *(float4*)(cp + ncol1) = o1;
        }
    }
}

// ---------------- persistent recurrence kernel ----------------
// R13 structure + three latency/jitter optimizations:
//  (1) ih prefetch one step AHEAD (DRAM latency never on the finalize path)
//  (2) parallel activation finalize: 32 lanes of warp 0 -> 3 shfl -> lanes<8
//  (3) nanosleep backoff on poll MISS only (hit path unchanged)
__global__ __launch_bounds__(1024, 1)
void recurrence(const float* __restrict__ encWhh, const float* __restrict__ decWhh)
{
    __shared__ float hs_sh[HID];
    __shared__ float part[32];

    const int tid = threadIdx.x;
    const int b = blockIdx.x;
    const int w = tid >> 5, l = tid & 31;
    const int gi = w >> 3, jrow = w & 7;
    const int grow = gi * HID + 8 * b + jrow;
    // ih element for this thread's finalize role (valid for tid<32): row index tid
    const int ihrow = (tid >> 3) * HID + 8 * b + (tid & 7);

    float Wreg[32];
    {
        const float* rp = encWhh + (size_t)grow * HID;
#pragma unroll
        for (int c = 0; c < 32; c++) Wreg[c] = __ldg(rp + l + 32 * c);
    }
    float c_reg = 0.0f;                      // cell state (lanes<8 of warp 0)
    float ihv = 0.0f;                        // ih value for the CURRENT step (warp 0)
    if (tid < 32) ihv = __ldg(g_ih_enc + ihrow);   // prefetch step 0
    __syncthreads();

    for (int sc = 0; sc < NSTEPS; sc++) {
        if (sc == T_SEQ) {                   // switch to decoder weights
            const float* rp = decWhh + (size_t)grow * HID;
#pragma unroll
            for (int c = 0; c < 32; c++) Wreg[c] = __ldg(rp + l + 32 * c);
        }
        const bool enc = sc < T_SEQ;
        const int tstep = enc ? sc : sc - T_SEQ;

        // --- acquire h(sc-1): immediate first load, backoff on miss ---
        float hval;
        if (sc == 0) {
            hval = 0.0f;
        } else {
            const unsigned long long* sp = &g_slots[((sc - 1) & 1) * HID + tid];
            const unsigned wantTag = (unsigned)(sc - 1);
            unsigned long long v = slot_load(sp);
            while ((unsigned)(v >> 32) != wantTag) {
                __nanosleep(64);
                v = slot_load(sp);
            }
            hval = __uint_as_float((unsigned)v);
        }
        hs_sh[tid] = hval;
        __syncthreads();

        // --- (Whh @ h)[grow]: 4 independent accumulators + warp reduce ---
        float s0 = 0.f, s1 = 0.f, s2 = 0.f, s3 = 0.f;
#pragma unroll
        for (int c = 0; c < 8; c++) {
            s0 = fmaf(Wreg[4*c + 0], hs_sh[l + 32 * (4*c + 0)], s0);
            s1 = fmaf(Wreg[4*c + 1], hs_sh[l + 32 * (4*c + 1)], s1);
            s2 = fmaf(Wreg[4*c + 2], hs_sh[l + 32 * (4*c + 2)], s2);
            s3 = fmaf(Wreg[4*c + 3], hs_sh[l + 32 * (4*c + 3)], s3);
        }
        float s = (s0 + s1) + (s2 + s3);
#pragma unroll
        for (int off = 16; off; off >>= 1) s += __shfl_xor_sync(0xffffffffu, s, off);
        if (l == 0) part[w] = s;
        __syncthreads();

        // --- finalize: parallel activations in warp 0, gather via shfl ---
        if (w == 0) {
            float pre = part[l] + ihv;       // row l preactivation
            float act = (l >= 16 && l < 24) ? tanh_f(pre) : sigm_f(pre);
            float af = __shfl_sync(0xffffffffu, act, (l & 7) + 8);
            float ag = __shfl_sync(0xffffffffu, act, (l & 7) + 16);
            float ao = __shfl_sync(0xffffffffu, act, (l & 7) + 24);
            if (l < 8) {
                c_reg = af * c_reg + act * ag;
                float h = ao * tanh_f(c_reg);
                unsigned long long pv = ((unsigned long long)(unsigned)sc << 32)
                                      | (unsigned long long)__float_as_uint(h);
                slot_store(&g_slots[(sc & 1) * HID + 8 * b + l], pv);
                if (!enc) g_hs[(size_t)tstep * HID + 8 * b + l] = h;
            }
            // prefetch ih for NEXT step (off the critical path)
            if (sc + 1 < NSTEPS) {
                const float* nb = (sc + 1 < T_SEQ) ? g_ih_enc : g_ih_dec;
                int nt = (sc + 1 < T_SEQ) ? sc + 1 : sc + 1 - T_SEQ;
                ihv = __ldg(nb + (size_t)nt * G4H + ihrow);
            }
        }
    }
}

// ---------------- tensor-core projection via mma.sync (bf16 hi/lo, 3 passes) ----
#define PJ_STRIDE 144
#define PJ_OPBYTES (128 * PJ_STRIDE)            // 18432 per operand
#define PJ_SMEM    (4 * PJ_OPBYTES)             // 73728

__global__ __launch_bounds__(256, 2)
void proj_mma(const float* __restrict__ bias, float* __restrict__ out)
{
    extern __shared__ char smc[];
    char* sAhi = smc;
    char* sAlo = smc + PJ_OPBYTES;
    char* sBhi = smc + 2 * PJ_OPBYTES;
    char* sBlo = smc + 3 * PJ_OPBYTES;

    const int tid = threadIdx.x;
    const int wid = tid >> 5, lane = tid & 31;
    const int g8 = lane >> 2, tg = lane & 3;
    const int wm = wid & 1, wn = wid >> 1;       // warp grid 2(m) x 4(n)
    const int n0 = blockIdx.x * 128;             // vocab tile
    const int m0 = blockIdx.y * 128;             // hs-row tile

    const char* gA_hi = (const char*)(g_hs_hi + (size_t)m0 * HID);
    const char* gA_lo = (const char*)(g_hs_lo + (size_t)m0 * HID);
    const char* gB_hi = (const char*)(g_w_hi + (size_t)n0 * HID);
    const char* gB_lo = (const char*)(g_w_lo + (size_t)n0 * HID);

    float c[4][4][4];
#pragma unroll
    for (int i = 0; i < 4; i++)
#pragma unroll
        for (int j = 0; j < 4; j++)
#pragma unroll
            for (int k = 0; k < 4; k++) c[i][j][k] = 0.0f;

    for (int ch = 0; ch < 16; ch++) {
        const int kbyte = ch * 128;              // 64 bf16 = 128 bytes per row
#pragma unroll
        for (int it = 0; it < 4; it++) {
            int g = tid + it * 256;              // 0..1023
            int row = g >> 3, gr = g & 7;
            size_t go = (size_t)row * (HID * 2) + kbyte + gr * 16;
            int so = row * PJ_STRIDE + gr * 16;
            *(uint4*)(sAhi + so) = *(const uint4*)(gA_hi + go);
            *(uint4*)(sAlo + so) = *(const uint4*)(gA_lo + go);
            *(uint4*)(sBhi + so) = *(const uint4*)(gB_hi + go);
            *(uint4*)(sBlo + so) = *(const uint4*)(gB_lo + go);
        }
        __syncthreads();

#pragma unroll
        for (int ks = 0; ks < 4; ks++) {
            unsigned bhi[4][2], blo[4][2];
#pragma unroll
            for (int nt = 0; nt < 4; nt++) {
                int o = (wn * 32 + nt * 8 + g8) * PJ_STRIDE + ks * 32 + tg * 4;
                bhi[nt][0] = *(const unsigned*)(sBhi + o);
                bhi[nt][1] = *(const unsigned*)(sBhi + o + 16);
                blo[nt][0] = *(const unsigned*)(sBlo + o);
                blo[nt][1] = *(const unsigned*)(sBlo + o + 16);
            }
#pragma unroll
            for (int mt = 0; mt < 4; mt++) {
                int o = (wm * 64 + mt * 16 + g8) * PJ_STRIDE + ks * 32 + tg * 4;
                unsigned ahi[4], alo[4];
                ahi[0] = *(const unsigned*)(sAhi + o);
                ahi[1] = *(const unsigned*)(sAhi + o + 8 * PJ_STRIDE);
                ahi[2] = *(const unsigned*)(sAhi + o + 16);
                ahi[3] = *(const unsigned*)(sAhi + o + 8 * PJ_STRIDE + 16);
                alo[0] = *(const unsigned*)(sAlo + o);
                alo[1] = *(const unsigned*)(sAlo + o + 8 * PJ_STRIDE);
                alo[2] = *(const unsigned*)(sAlo + o + 16);
                alo[3] = *(const unsigned*)(sAlo + o + 8 * PJ_STRIDE + 16);
#pragma unroll
                for (int nt = 0; nt < 4; nt++) {
                    mma16816(c[mt][nt], ahi, bhi[nt]);   // hi*hi
                    mma16816(c[mt][nt], ahi, blo[nt]);   // hi*lo
                    mma16816(c[mt][nt], alo, bhi[nt]);   // lo*hi
                }
            }
        }
        __syncthreads();
    }

#pragma unroll
    for (int mt = 0; mt < 4; mt++) {
        int row = m0 + wm * 64 + mt * 16 + g8;
#pragma unroll
        for (int nt = 0; nt < 4; nt++) {
            int col = n0 + wn * 32 + nt * 8 + tg * 2;
            float b0 = __ldg(bias + col), b1 = __ldg(bias + col + 1);
            if (row < T_SEQ - 1) {
                float2 o; o.x = c[mt][nt][0] + b0; o.y = c[mt][nt][1] + b1;
                *(float2*)(out + (size_t)row * VOC + col) = o;
            }
            if (row + 8 < T_SEQ - 1) {
                float2 o; o.x = c[mt][nt][2] + b0; o.y = c[mt][nt][3] + b1;
                *(float2*)(out + (size_t)(row + 8) * VOC + col) = o;
            }
        }
    }
}

// ---------------- launch ----------------
extern "C" void kernel_launch(void* const* d_in, const int* in_sizes, int n_in,
                              void* d_out, int out_size)
{
    const int*   seq     = (const int*)  d_in[0];
    const float* enc_emb = (const float*)d_in[1];   // [V, 512]
    const float* enc_Wih = (const float*)d_in[2];   // [4H, 512]
    const float* enc_Whh = (const float*)d_in[3];   // [4H, 1024]
    const float* enc_bih = (const float*)d_in[4];
    const float* enc_bhh = (const float*)d_in[5];
    const float* dec_emb = (const float*)d_in[6];
    const float* dec_Wih = (const float*)d_in[7];
    const float* dec_Whh = (const float*)d_in[8];
    const float* dec_bih = (const float*)d_in[9];
    const float* dec_bhh = (const float*)d_in[10];
    const float* out_W   = (const float*)d_in[11];  // [V, 1024]
    const float* out_b   = (const float*)d_in[12];
    float* out = (float*)d_out;

    float *ih_enc, *ih_dec, *hsbuf;
    __nv_bfloat16 *hshi, *hslo, *whi, *wlo;
    cudaGetSymbolAddress((void**)&ih_enc, g_ih_enc);
    cudaGetSymbolAddress((void**)&ih_dec, g_ih_dec);
    cudaGetSymbolAddress((void**)&hsbuf,  g_hs);
    cudaGetSymbolAddress((void**)&hshi,   g_hs_hi);
    cudaGetSymbolAddress((void**)&hslo,   g_hs_lo);
    cudaGetSymbolAddress((void**)&whi,    g_w_hi);
    cudaGetSymbolAddress((void**)&wlo,    g_w_lo);

    init_kernel<<<2, 1024>>>();

    // out_W -> bf16 hi/lo (independent of recurrence)
    {
        size_t n = (size_t)VOC * HID;
        conv_split<<<(unsigned)((n + 255) / 256), 256>>>(out_W, whi, wlo, n, n);
    }

    // Precompute input gates (K = EMB = 512)
    gemm_nt<<<dim3(G4H / 128, T_SEQ / 128), 256>>>(
        nullptr, enc_emb, seq, enc_Wih, enc_bih, enc_bhh, ih_enc, T_SEQ, G4H, EMB);
    gemm_nt<<<dim3(G4H / 128, (T_SEQ - 1 + 127) / 128), 256>>>(
        nullptr, dec_emb, seq, dec_Wih, dec_bih, dec_bhh, ih_dec, T_SEQ - 1, G4H, EMB);

    // Sequential encoder+decoder scan
    recurrence<<<NBLK, 1024>>>(enc_Whh, dec_Whh);

    // hs -> bf16 hi/lo (row 4095 zero-padded)
    {
        size_t n = (size_t)MROWS * HID, sn = (size_t)(T_SEQ - 1) * HID;
        conv_split<<<(unsigned)((n + 255) / 256), 256>>>(hsbuf, hshi, hslo, n, sn);
    }

    // Tensor-core projection: [4095, 32000] via mma.sync bf16 hi/lo
    cudaFuncSetAttribute(proj_mma, cudaFuncAttributeMaxDynamicSharedMemorySize, PJ_SMEM);
    proj_mma<<<dim3(VOC / 128, MROWS / 128), 256, PJ_SMEM>>>(out_b, out);
}